// round 1
// baseline (speedup 1.0000x reference)
#include <cuda_runtime.h>
#include <cuda_bf16.h>
#include <math.h>

// ---------------- problem constants ----------------
#define B_    4
#define IMG_H 1024
#define IMG_W 1536

#define H1 512
#define W1 768
#define H2 256
#define W2 384
#define H3 128
#define W3 192
#define HF 64
#define WF 96

#define C1 32
#define C2 64
#define C3 128
#define C4 128

#define OUTC  64
#define DBINS 16
#define NYV 256
#define NXV 256
#define SV  (NYV*NXV)

// ---------------- scratch (static device globals; no allocation) ----------------
__device__ float g_x1[B_ * C1 * H1 * W1];     // 201 MB
__device__ float g_x2[B_ * C2 * H2 * W2];     // 100 MB
__device__ float g_x3[B_ * C3 * H3 * W3];     //  50 MB
__device__ float g_x4[B_ * C4 * HF * WF];     // 12.6 MB
__device__ float g_fh[B_ * C4 * HF * WF];     // 12.6 MB
__device__ float g_canvas[B_ * SV * OUTC];    //  67 MB
__device__ float g_wacc[B_ * SV];             //   1 MB

// ---------------- zero canvas ----------------
__global__ void zero_kernel() {
    int n1 = B_ * SV * OUTC;
    int n2 = B_ * SV;
    for (int i = blockIdx.x * blockDim.x + threadIdx.x; i < n1; i += gridDim.x * blockDim.x)
        g_canvas[i] = 0.f;
    for (int i = blockIdx.x * blockDim.x + threadIdx.x; i < n2; i += gridDim.x * blockDim.x)
        g_wacc[i] = 0.f;
}

// ---------------- direct 3x3 conv + folded-BN + ReLU ----------------
// layout NCHW. pad=1. interior fast path (no bounds checks).
__global__ void conv3x3_bn_relu(const float* __restrict__ in, const float* __restrict__ wt,
                                const float* __restrict__ sc, const float* __restrict__ bi,
                                float* __restrict__ out,
                                int CIN, int H, int W, int OC, int OH, int OW, int stride)
{
    int idx = blockIdx.x * blockDim.x + threadIdx.x;
    int total = B_ * OC * OH * OW;
    if (idx >= total) return;
    int ow = idx % OW;
    int t  = idx / OW;
    int oh = t % OH;  t /= OH;
    int oc = t % OC;
    int b  = t / OC;

    int ih0 = oh * stride - 1;
    int iw0 = ow * stride - 1;
    const float* wbase = wt + oc * CIN * 9;
    const float* ibase = in + (size_t)b * CIN * H * W;
    float acc = 0.f;

    bool interior = (ih0 >= 0) && (ih0 + 2 < H) && (iw0 >= 0) && (iw0 + 2 < W);
    if (interior) {
        const float* ip = ibase + ih0 * W + iw0;
        const float* wp = wbase;
        for (int ic = 0; ic < CIN; ic++) {
            float w0 = wp[0], w1 = wp[1], w2 = wp[2];
            float w3 = wp[3], w4 = wp[4], w5 = wp[5];
            float w6 = wp[6], w7 = wp[7], w8 = wp[8];
            acc += ip[0]       * w0 + ip[1]       * w1 + ip[2]       * w2;
            acc += ip[W]       * w3 + ip[W + 1]   * w4 + ip[W + 2]   * w5;
            acc += ip[2 * W]   * w6 + ip[2 * W + 1] * w7 + ip[2 * W + 2] * w8;
            ip += H * W;
            wp += 9;
        }
    } else {
        for (int ic = 0; ic < CIN; ic++) {
            const float* ip = ibase + (size_t)ic * H * W;
            const float* wp = wbase + ic * 9;
            #pragma unroll
            for (int kh = 0; kh < 3; kh++) {
                int ih = ih0 + kh;
                if ((unsigned)ih >= (unsigned)H) continue;
                #pragma unroll
                for (int kw = 0; kw < 3; kw++) {
                    int iw = iw0 + kw;
                    if ((unsigned)iw >= (unsigned)W) continue;
                    acc += ip[ih * W + iw] * wp[kh * 3 + kw];
                }
            }
        }
    }
    float v = acc * sc[oc] + bi[oc];
    out[idx] = fmaxf(v, 0.f);
}

// ---------------- heads (1x1 convs) + depth lift + backprojection + gaussian splat ----------------
// one block (128 threads) per feature-grid pixel.
__global__ void heads_splat(const float* __restrict__ x4, const float* __restrict__ fh,
                            const float* __restrict__ fw2, const float* __restrict__ fb2,
                            const float* __restrict__ dw,  const float* __restrict__ db,
                            const float* __restrict__ oww, const float* __restrict__ ob,
                            const float* __restrict__ camK, const float* __restrict__ Tlc,
                            const int* __restrict__ imgh, const int* __restrict__ imgw)
{
    const int pix = blockIdx.x;                 // b*HF*WF + h*WF + w
    const int w   = pix % WF;
    int t = pix / WF;
    const int h = t % HF;
    const int b = t / HF;
    const int tid = threadIdx.x;

    __shared__ float sx4[C4];
    __shared__ float sfh[C4];
    __shared__ float sfeat[OUTC];
    __shared__ float sdl[DBINS];
    __shared__ float sprm[4];   // 0: opacity, 1: base_w, 2: xi(bits), 3: yi(bits)

    int off = ((b * C4 + tid) * HF + h) * WF + w;
    sx4[tid] = x4[off];
    sfh[tid] = fh[off];
    __syncthreads();

    if (tid < OUTC) {
        float a = 0.f;
        const float* wr = fw2 + tid * C4;
        #pragma unroll 8
        for (int k = 0; k < C4; k++) a += wr[k] * sfh[k];
        sfeat[tid] = a + fb2[tid];
    } else if (tid < OUTC + DBINS) {
        int d = tid - OUTC;
        float a = 0.f;
        const float* wr = dw + d * C4;
        #pragma unroll 8
        for (int k = 0; k < C4; k++) a += wr[k] * sx4[k];
        sdl[d] = a + db[d];
    } else if (tid == OUTC + DBINS) {
        float a = 0.f;
        #pragma unroll 8
        for (int k = 0; k < C4; k++) a += oww[k] * sx4[k];
        sprm[0] = 1.f / (1.f + expf(-(a + ob[0])));
    }
    __syncthreads();

    if (tid == 0) {
        // softmax expectation over depth bins
        float m = -1e30f;
        #pragma unroll
        for (int d = 0; d < DBINS; d++) m = fmaxf(m, sdl[d]);
        float sum = 0.f, zz = 0.f;
        #pragma unroll
        for (int d = 0; d < DBINS; d++) {
            float e = expf(sdl[d] - m);
            sum += e;
            zz  += e * (1.f + (float)d * (59.f / 15.f));
        }
        float z = zz / sum;

        float ihf = (float)imgh[0];
        float iwf = (float)imgw[0];
        float ys = ((float)h + 0.5f) * (ihf / (float)HF);
        float xs = ((float)w + 0.5f) * (iwf / (float)WF);

        const float* K = camK + b * 9;
        float fx = fmaxf(K[0], 1e-6f), fy = fmaxf(K[4], 1e-6f);
        float cx = K[2], cy = K[5];
        float xc = (xs - cx) * z / fx;
        float yc = (ys - cy) * z / fy;

        const float* T = Tlc + b * 16;
        float lx = T[0] * xc + T[1] * yc + T[2]  * z + T[3];
        float ly = T[4] * xc + T[5] * yc + T[6]  * z + T[7];
        float lz = T[8] * xc + T[9] * yc + T[10] * z + T[11];

        int xi = (int)floorf((lx + 51.2f) * 2.5f);   // /0.4
        int yi = (int)floorf((ly + 51.2f) * 2.5f);
        bool inb = (xi >= 0) && (xi < NXV) && (yi >= 0) && (yi < NYV) &&
                   (lz >= -5.f) && (lz < 3.f);
        float op = sprm[0];
        float bw = (op >= 0.05f && inb) ? op : 0.f;
        sprm[1] = bw;
        sprm[2] = __int_as_float(xi);
        sprm[3] = __int_as_float(yi);
    }
    __syncthreads();

    float bw = sprm[1];
    if (bw <= 0.f) return;
    int xi = __float_as_int(sprm[2]);
    int yi = __float_as_int(sprm[3]);

    #pragma unroll
    for (int tap = 0; tap < 9; tap++) {
        int dy = tap / 3 - 1;
        int dx = tap % 3 - 1;
        int ty = yi + dy;
        int tx = xi + dx;
        if ((unsigned)tx >= (unsigned)NXV || (unsigned)ty >= (unsigned)NYV) continue;
        float kwv = expf(-(float)(dx * dx + dy * dy) * (1.f / 1.28f));
        float sw = bw * kwv;
        int vox = b * SV + ty * NXV + tx;
        if (tid < OUTC) atomicAdd(&g_canvas[vox * OUTC + tid], sfeat[tid] * sw);
        if (tid == OUTC) atomicAdd(&g_wacc[vox], sw);
    }
}

// ---------------- normalize + transpose (pix, C) -> (B, C, NY, NX) ----------------
__global__ void finalize_kernel(float* __restrict__ out)
{
    __shared__ float tile[OUTC][33];
    int gp  = blockIdx.x * 32;          // starting global pixel (b*SV + y*NXV + x0)
    int tid = threadIdx.x;              // 256 threads

    for (int i = tid; i < 32 * OUTC; i += 256) {
        int p = i >> 6;                 // 0..31
        int c = i & 63;
        float wv  = g_wacc[gp + p];
        float inv = (wv > 0.f) ? (1.f / fmaxf(wv, 1e-6f)) : 0.f;
        tile[c][p] = g_canvas[(gp + p) * OUTC + c] * inv;
    }
    __syncthreads();

    int b  = gp >> 16;
    int p0 = gp & 65535;
    for (int i = tid; i < OUTC * 32; i += 256) {
        int c = i >> 5;
        int x = i & 31;
        out[(((b * OUTC) + c) << 16) + p0 + x] = tile[c][x];
    }
}

// ---------------- launch ----------------
extern "C" void kernel_launch(void* const* d_in, const int* in_sizes, int n_in,
                              void* d_out, int out_size)
{
    const float* images = (const float*)d_in[0];
    const float* camK   = (const float*)d_in[1];
    const float* Tlc    = (const float*)d_in[2];
    const float* w1 = (const float*)d_in[3];
    const float* s1 = (const float*)d_in[4];
    const float* b1 = (const float*)d_in[5];
    const float* w2 = (const float*)d_in[6];
    const float* s2 = (const float*)d_in[7];
    const float* b2 = (const float*)d_in[8];
    const float* w3 = (const float*)d_in[9];
    const float* s3 = (const float*)d_in[10];
    const float* b3 = (const float*)d_in[11];
    const float* w4 = (const float*)d_in[12];
    const float* s4 = (const float*)d_in[13];
    const float* b4 = (const float*)d_in[14];
    const float* fw1 = (const float*)d_in[15];
    const float* fs1 = (const float*)d_in[16];
    const float* fb1 = (const float*)d_in[17];
    const float* fw2 = (const float*)d_in[18];
    const float* fb2 = (const float*)d_in[19];
    const float* dw  = (const float*)d_in[20];
    const float* db  = (const float*)d_in[21];
    const float* ow  = (const float*)d_in[22];
    const float* ob  = (const float*)d_in[23];
    const int* imgh  = (const int*)d_in[24];
    const int* imgw  = (const int*)d_in[25];
    float* out = (float*)d_out;

    float* x1; cudaGetSymbolAddress((void**)&x1, g_x1);
    float* x2; cudaGetSymbolAddress((void**)&x2, g_x2);
    float* x3; cudaGetSymbolAddress((void**)&x3, g_x3);
    float* x4; cudaGetSymbolAddress((void**)&x4, g_x4);
    float* fhp; cudaGetSymbolAddress((void**)&fhp, g_fh);

    zero_kernel<<<2048, 256>>>();

    {
        int total = B_ * C1 * H1 * W1;
        conv3x3_bn_relu<<<(total + 255) / 256, 256>>>(images, w1, s1, b1, x1,
                                                      3, IMG_H, IMG_W, C1, H1, W1, 2);
    }
    {
        int total = B_ * C2 * H2 * W2;
        conv3x3_bn_relu<<<(total + 255) / 256, 256>>>(x1, w2, s2, b2, x2,
                                                      C1, H1, W1, C2, H2, W2, 2);
    }
    {
        int total = B_ * C3 * H3 * W3;
        conv3x3_bn_relu<<<(total + 255) / 256, 256>>>(x2, w3, s3, b3, x3,
                                                      C2, H2, W2, C3, H3, W3, 2);
    }
    {
        int total = B_ * C4 * HF * WF;
        conv3x3_bn_relu<<<(total + 255) / 256, 256>>>(x3, w4, s4, b4, x4,
                                                      C3, H3, W3, C4, HF, WF, 2);
    }
    {
        int total = B_ * C4 * HF * WF;
        conv3x3_bn_relu<<<(total + 255) / 256, 256>>>(x4, fw1, fs1, fb1, fhp,
                                                      C4, HF, WF, C4, HF, WF, 1);
    }

    heads_splat<<<B_ * HF * WF, 128>>>(x4, fhp, fw2, fb2, dw, db, ow, ob,
                                       camK, Tlc, imgh, imgw);

    finalize_kernel<<<B_ * SV / 32, 256>>>(out);
}

// round 2
// speedup vs baseline: 6.1405x; 6.1405x over previous
#include <cuda_runtime.h>
#include <cuda_bf16.h>
#include <math.h>

// ---------------- problem constants ----------------
#define B_    4
#define IMG_H 1024
#define IMG_W 1536

#define H1 512
#define W1 768
#define H2 256
#define W2 384
#define H3 128
#define W3 192
#define HF 64
#define WF 96

#define C1 32
#define C2 64
#define C3 128
#define C4 128

#define OUTC  64
#define DBINS 16
#define NYV 256
#define NXV 256
#define SV  (NYV*NXV)

// ---------------- scratch (static device globals; no allocation) ----------------
__device__ float g_im[(size_t)B_ * IMG_H * IMG_W * 4];   // NHWC padded C=4, 100 MB
__device__ float g_x1[(size_t)B_ * H1 * W1 * C1];        // NHWC, 201 MB
__device__ float g_x2[(size_t)B_ * H2 * W2 * C2];        // NHWC, 100 MB
__device__ float g_x3[(size_t)B_ * H3 * W3 * C3];        // NHWC,  50 MB
__device__ float g_x4[(size_t)B_ * HF * WF * C4];        // NHWC, 12.6 MB
__device__ float g_fh[(size_t)B_ * HF * WF * C4];        // NHWC, 12.6 MB
__device__ float g_canvas[(size_t)B_ * SV * OUTC];       // 67 MB
__device__ float g_wacc[B_ * SV];                        //  1 MB

// transposed weights [K = 9*CPAD][OC]
__device__ float g_wt1[36 * 32];
__device__ float g_wt2[288 * 64];
__device__ float g_wt3[576 * 128];
__device__ float g_wt4[1152 * 128];
__device__ float g_wt5[1152 * 128];

// ---------------- zero canvas ----------------
__global__ void zero_kernel() {
    int n1 = B_ * SV * OUTC;
    int n2 = B_ * SV;
    for (int i = blockIdx.x * blockDim.x + threadIdx.x; i < n1; i += gridDim.x * blockDim.x)
        g_canvas[i] = 0.f;
    for (int i = blockIdx.x * blockDim.x + threadIdx.x; i < n2; i += gridDim.x * blockDim.x)
        g_wacc[i] = 0.f;
}

// ---------------- weight transpose: OIHW -> [tap*CPAD+ic][OC] ----------------
__global__ void wprep(const float* __restrict__ w, float* __restrict__ o,
                      int CIN, int CPAD, int OC, int total)
{
    int i = blockIdx.x * blockDim.x + threadIdx.x;
    if (i >= total) return;
    int oc = i % OC;
    int k  = i / OC;
    int tap = k / CPAD;
    int ic  = k % CPAD;
    o[i] = (ic < CIN) ? w[(oc * CIN + ic) * 9 + tap] : 0.f;
}

// ---------------- images NCHW -> NHWC padded C=4 ----------------
__global__ void im2nhwc(const float* __restrict__ im)
{
    int i = blockIdx.x * blockDim.x + threadIdx.x;
    const int HW = IMG_H * IMG_W;
    if (i >= B_ * HW) return;
    int b = i / HW;
    int p = i % HW;
    const float* base = im + (size_t)b * 3 * HW + p;
    float4 v;
    v.x = base[0];
    v.y = base[HW];
    v.z = base[2 * HW];
    v.w = 0.f;
    *(float4*)&g_im[(size_t)i * 4] = v;
}

// ---------------- conv1: direct, NHWC-in (padded C=4), NHWC-out, 32oc/thread ----------------
__global__ __launch_bounds__(256) void conv1_kernel(const float* __restrict__ sc,
                                                    const float* __restrict__ bi)
{
    __shared__ float ws[36 * 32];
    __shared__ float ssc[32], sbi[32];
    int tid = threadIdx.x;
    for (int i = tid; i < 36 * 32; i += 256) ws[i] = g_wt1[i];
    if (tid < 32) { ssc[tid] = sc[tid]; sbi[tid] = bi[tid]; }
    __syncthreads();

    int p = blockIdx.x * 256 + tid;           // pixel in (b, oh, ow) order
    const int HW = H1 * W1;
    int b  = p / HW;
    int r  = p % HW;
    int oh = r / W1;
    int ow = r % W1;
    int ihb = oh * 2 - 1;
    int iwb = ow * 2 - 1;

    float4 patch[9];
    #pragma unroll
    for (int t = 0; t < 9; t++) {
        int kh = t / 3, kw = t % 3;
        int ih = ihb + kh, iw = iwb + kw;
        float4 v = make_float4(0.f, 0.f, 0.f, 0.f);
        if ((unsigned)ih < (unsigned)IMG_H && (unsigned)iw < (unsigned)IMG_W)
            v = *(const float4*)&g_im[(((size_t)b * IMG_H + ih) * IMG_W + iw) * 4];
        patch[t] = v;
    }

    float4 acc[8];
    #pragma unroll
    for (int q = 0; q < 8; q++) acc[q] = make_float4(0.f, 0.f, 0.f, 0.f);

    #pragma unroll
    for (int t = 0; t < 9; t++) {
        #pragma unroll
        for (int ic = 0; ic < 4; ic++) {
            float a = (ic == 0) ? patch[t].x : (ic == 1) ? patch[t].y :
                      (ic == 2) ? patch[t].z : patch[t].w;
            int k = t * 4 + ic;
            #pragma unroll
            for (int q = 0; q < 8; q++) {
                float4 wv = ((float4*)ws)[k * 8 + q];
                acc[q].x += a * wv.x;
                acc[q].y += a * wv.y;
                acc[q].z += a * wv.z;
                acc[q].w += a * wv.w;
            }
        }
    }

    float* outp = &g_x1[(size_t)p * C1];
    #pragma unroll
    for (int q = 0; q < 8; q++) {
        float4 v;
        v.x = fmaxf(acc[q].x * ssc[q * 4 + 0] + sbi[q * 4 + 0], 0.f);
        v.y = fmaxf(acc[q].y * ssc[q * 4 + 1] + sbi[q * 4 + 1], 0.f);
        v.z = fmaxf(acc[q].z * ssc[q * 4 + 2] + sbi[q * 4 + 2], 0.f);
        v.w = fmaxf(acc[q].w * ssc[q * 4 + 3] + sbi[q * 4 + 3], 0.f);
        *(float4*)&outp[q * 4] = v;
    }
}

// ---------------- implicit-GEMM conv (NHWC in/out), BM=128 pix, BN=64 oc, BK=32 ----------------
template <int CIN, int OC, int S, int H, int W, int OH, int OW>
__global__ __launch_bounds__(256) void conv_gemm(const float* __restrict__ in,
                                                 const float* __restrict__ wt,
                                                 const float* __restrict__ sc,
                                                 const float* __restrict__ bi,
                                                 float* __restrict__ out)
{
    constexpr int NCH = CIN / 32;       // k-chunks per tap
    constexpr int ITERS = 9 * NCH;

    __shared__ float As[128 * 33];      // [pix][k] padded
    __shared__ float Bs[32 * 64];       // [k][oc]

    const int tid  = threadIdx.x;
    const int pix0 = blockIdx.x * 128;
    const int oc0  = blockIdx.y * 64;

    // A-load mapping: 32 load-pixels x 8 segments of 4 k
    const int lp  = tid >> 3;
    const int seg = tid & 7;
    int ihb[4], iwb[4], basei[4];
    #pragma unroll
    for (int i = 0; i < 4; i++) {
        int p = pix0 + lp + 32 * i;
        int b = p / (OH * OW);
        int r = p % (OH * OW);
        int oh = r / OW;
        int ow = r % OW;
        ihb[i] = oh * S - 1;
        iwb[i] = ow * S - 1;
        basei[i] = ((b * H + ihb[i]) * W + iwb[i]) * CIN;
    }

    // B-load mapping
    const int krow  = tid >> 4;
    const int ocseg = tid & 15;

    // compute mapping: 16 pixel-groups x 16 oc-groups
    const int pg = tid >> 4;
    const int og = tid & 15;

    float4 acc[8];
    #pragma unroll
    for (int r = 0; r < 8; r++) acc[r] = make_float4(0.f, 0.f, 0.f, 0.f);

    float4 aR[4];
    float4 bR[2];

    auto loadg = [&](int it) {
        int tap   = it / NCH;
        int chunk = it % NCH;
        int kh = tap / 3, kw = tap % 3;
        #pragma unroll
        for (int i = 0; i < 4; i++) {
            float4 v = make_float4(0.f, 0.f, 0.f, 0.f);
            if ((unsigned)(ihb[i] + kh) < (unsigned)H &&
                (unsigned)(iwb[i] + kw) < (unsigned)W)
                v = *(const float4*)&in[basei[i] + (kh * W + kw) * CIN + chunk * 32 + seg * 4];
            aR[i] = v;
        }
        bR[0] = *(const float4*)&wt[(it * 32 + krow)      * OC + oc0 + ocseg * 4];
        bR[1] = *(const float4*)&wt[(it * 32 + krow + 16) * OC + oc0 + ocseg * 4];
    };

    loadg(0);
    for (int it = 0; it < ITERS; it++) {
        __syncthreads();
        #pragma unroll
        for (int i = 0; i < 4; i++) {
            int row = lp + 32 * i;
            As[row * 33 + seg * 4 + 0] = aR[i].x;
            As[row * 33 + seg * 4 + 1] = aR[i].y;
            As[row * 33 + seg * 4 + 2] = aR[i].z;
            As[row * 33 + seg * 4 + 3] = aR[i].w;
        }
        ((float4*)Bs)[krow * 16 + ocseg]        = bR[0];
        ((float4*)Bs)[(krow + 16) * 16 + ocseg] = bR[1];
        __syncthreads();
        if (it + 1 < ITERS) loadg(it + 1);

        #pragma unroll
        for (int k = 0; k < 32; k++) {
            float4 b4 = ((float4*)Bs)[k * 16 + og];
            #pragma unroll
            for (int r = 0; r < 8; r++) {
                float a = As[(pg * 8 + r) * 33 + k];
                acc[r].x += a * b4.x;
                acc[r].y += a * b4.y;
                acc[r].z += a * b4.z;
                acc[r].w += a * b4.w;
            }
        }
    }

    float4 s4 = *(const float4*)&sc[oc0 + og * 4];
    float4 b4 = *(const float4*)&bi[oc0 + og * 4];
    #pragma unroll
    for (int r = 0; r < 8; r++) {
        int p = pix0 + pg * 8 + r;
        float4 v;
        v.x = fmaxf(acc[r].x * s4.x + b4.x, 0.f);
        v.y = fmaxf(acc[r].y * s4.y + b4.y, 0.f);
        v.z = fmaxf(acc[r].z * s4.z + b4.z, 0.f);
        v.w = fmaxf(acc[r].w * s4.w + b4.w, 0.f);
        *(float4*)&out[(size_t)p * OC + oc0 + og * 4] = v;
    }
}

// ---------------- heads (1x1 convs) + depth lift + backprojection + gaussian splat ----------------
__global__ void heads_splat(const float* __restrict__ x4, const float* __restrict__ fh,
                            const float* __restrict__ fw2, const float* __restrict__ fb2,
                            const float* __restrict__ dw,  const float* __restrict__ db,
                            const float* __restrict__ oww, const float* __restrict__ ob,
                            const float* __restrict__ camK, const float* __restrict__ Tlc,
                            const int* __restrict__ imgh, const int* __restrict__ imgw)
{
    const int pix = blockIdx.x;                 // b*HF*WF + h*WF + w
    const int w   = pix % WF;
    int t = pix / WF;
    const int h = t % HF;
    const int b = t / HF;
    const int tid = threadIdx.x;

    __shared__ float sx4[C4];
    __shared__ float sfh[C4];
    __shared__ float sfeat[OUTC];
    __shared__ float sdl[DBINS];
    __shared__ float sprm[4];

    // NHWC reads: contiguous per pixel
    sx4[tid] = x4[(size_t)pix * C4 + tid];
    sfh[tid] = fh[(size_t)pix * C4 + tid];
    __syncthreads();

    if (tid < OUTC) {
        float a = 0.f;
        const float* wr = fw2 + tid * C4;
        #pragma unroll 8
        for (int k = 0; k < C4; k++) a += wr[k] * sfh[k];
        sfeat[tid] = a + fb2[tid];
    } else if (tid < OUTC + DBINS) {
        int d = tid - OUTC;
        float a = 0.f;
        const float* wr = dw + d * C4;
        #pragma unroll 8
        for (int k = 0; k < C4; k++) a += wr[k] * sx4[k];
        sdl[d] = a + db[d];
    } else if (tid == OUTC + DBINS) {
        float a = 0.f;
        #pragma unroll 8
        for (int k = 0; k < C4; k++) a += oww[k] * sx4[k];
        sprm[0] = 1.f / (1.f + expf(-(a + ob[0])));
    }
    __syncthreads();

    if (tid == 0) {
        float m = -1e30f;
        #pragma unroll
        for (int d = 0; d < DBINS; d++) m = fmaxf(m, sdl[d]);
        float sum = 0.f, zz = 0.f;
        #pragma unroll
        for (int d = 0; d < DBINS; d++) {
            float e = expf(sdl[d] - m);
            sum += e;
            zz  += e * (1.f + (float)d * (59.f / 15.f));
        }
        float z = zz / sum;

        float ihf = (float)imgh[0];
        float iwf = (float)imgw[0];
        float ys = ((float)h + 0.5f) * (ihf / (float)HF);
        float xs = ((float)w + 0.5f) * (iwf / (float)WF);

        const float* K = camK + b * 9;
        float fx = fmaxf(K[0], 1e-6f), fy = fmaxf(K[4], 1e-6f);
        float cx = K[2], cy = K[5];
        float xc = (xs - cx) * z / fx;
        float yc = (ys - cy) * z / fy;

        const float* T = Tlc + b * 16;
        float lx = T[0] * xc + T[1] * yc + T[2]  * z + T[3];
        float ly = T[4] * xc + T[5] * yc + T[6]  * z + T[7];
        float lz = T[8] * xc + T[9] * yc + T[10] * z + T[11];

        int xi = (int)floorf((lx + 51.2f) * 2.5f);
        int yi = (int)floorf((ly + 51.2f) * 2.5f);
        bool inb = (xi >= 0) && (xi < NXV) && (yi >= 0) && (yi < NYV) &&
                   (lz >= -5.f) && (lz < 3.f);
        float op = sprm[0];
        float bw = (op >= 0.05f && inb) ? op : 0.f;
        sprm[1] = bw;
        sprm[2] = __int_as_float(xi);
        sprm[3] = __int_as_float(yi);
    }
    __syncthreads();

    float bw = sprm[1];
    if (bw <= 0.f) return;
    int xi = __float_as_int(sprm[2]);
    int yi = __float_as_int(sprm[3]);

    #pragma unroll
    for (int tap = 0; tap < 9; tap++) {
        int dy = tap / 3 - 1;
        int dx = tap % 3 - 1;
        int ty = yi + dy;
        int tx = xi + dx;
        if ((unsigned)tx >= (unsigned)NXV || (unsigned)ty >= (unsigned)NYV) continue;
        float kwv = expf(-(float)(dx * dx + dy * dy) * (1.f / 1.28f));
        float sw = bw * kwv;
        int vox = b * SV + ty * NXV + tx;
        if (tid < OUTC) atomicAdd(&g_canvas[(size_t)vox * OUTC + tid], sfeat[tid] * sw);
        if (tid == OUTC) atomicAdd(&g_wacc[vox], sw);
    }
}

// ---------------- normalize + transpose (pix, C) -> (B, C, NY, NX) ----------------
__global__ void finalize_kernel(float* __restrict__ out)
{
    __shared__ float tile[OUTC][33];
    int gp  = blockIdx.x * 32;
    int tid = threadIdx.x;              // 256 threads

    for (int i = tid; i < 32 * OUTC; i += 256) {
        int p = i >> 6;
        int c = i & 63;
        float wv  = g_wacc[gp + p];
        float inv = (wv > 0.f) ? (1.f / fmaxf(wv, 1e-6f)) : 0.f;
        tile[c][p] = g_canvas[(size_t)(gp + p) * OUTC + c] * inv;
    }
    __syncthreads();

    int b  = gp >> 16;
    int p0 = gp & 65535;
    for (int i = tid; i < OUTC * 32; i += 256) {
        int c = i >> 5;
        int x = i & 31;
        out[(((b * OUTC) + c) << 16) + p0 + x] = tile[c][x];
    }
}

// ---------------- launch ----------------
extern "C" void kernel_launch(void* const* d_in, const int* in_sizes, int n_in,
                              void* d_out, int out_size)
{
    const float* images = (const float*)d_in[0];
    const float* camK   = (const float*)d_in[1];
    const float* Tlc    = (const float*)d_in[2];
    const float* w1 = (const float*)d_in[3];
    const float* s1 = (const float*)d_in[4];
    const float* b1 = (const float*)d_in[5];
    const float* w2 = (const float*)d_in[6];
    const float* s2 = (const float*)d_in[7];
    const float* b2 = (const float*)d_in[8];
    const float* w3 = (const float*)d_in[9];
    const float* s3 = (const float*)d_in[10];
    const float* b3 = (const float*)d_in[11];
    const float* w4 = (const float*)d_in[12];
    const float* s4 = (const float*)d_in[13];
    const float* b4 = (const float*)d_in[14];
    const float* fw1 = (const float*)d_in[15];
    const float* fs1 = (const float*)d_in[16];
    const float* fb1 = (const float*)d_in[17];
    const float* fw2 = (const float*)d_in[18];
    const float* fb2 = (const float*)d_in[19];
    const float* dw  = (const float*)d_in[20];
    const float* db  = (const float*)d_in[21];
    const float* ow  = (const float*)d_in[22];
    const float* ob  = (const float*)d_in[23];
    const int* imgh  = (const int*)d_in[24];
    const int* imgw  = (const int*)d_in[25];
    float* out = (float*)d_out;

    float* x1;  cudaGetSymbolAddress((void**)&x1,  g_x1);
    float* x2;  cudaGetSymbolAddress((void**)&x2,  g_x2);
    float* x3;  cudaGetSymbolAddress((void**)&x3,  g_x3);
    float* x4;  cudaGetSymbolAddress((void**)&x4,  g_x4);
    float* fhp; cudaGetSymbolAddress((void**)&fhp, g_fh);
    float* wt1; cudaGetSymbolAddress((void**)&wt1, g_wt1);
    float* wt2; cudaGetSymbolAddress((void**)&wt2, g_wt2);
    float* wt3; cudaGetSymbolAddress((void**)&wt3, g_wt3);
    float* wt4; cudaGetSymbolAddress((void**)&wt4, g_wt4);
    float* wt5; cudaGetSymbolAddress((void**)&wt5, g_wt5);

    // weight transposes (tiny)
    wprep<<<(36 * 32 + 255) / 256, 256>>>(w1, wt1, 3, 4, 32, 36 * 32);
    wprep<<<(288 * 64 + 255) / 256, 256>>>(w2, wt2, 32, 32, 64, 288 * 64);
    wprep<<<(576 * 128 + 255) / 256, 256>>>(w3, wt3, 64, 64, 128, 576 * 128);
    wprep<<<(1152 * 128 + 255) / 256, 256>>>(w4, wt4, 128, 128, 128, 1152 * 128);
    wprep<<<(1152 * 128 + 255) / 256, 256>>>(fw1, wt5, 128, 128, 128, 1152 * 128);

    im2nhwc<<<(B_ * IMG_H * IMG_W + 255) / 256, 256>>>(images);
    zero_kernel<<<2048, 256>>>();

    conv1_kernel<<<B_ * H1 * W1 / 256, 256>>>(s1, b1);

    conv_gemm<C1, C2, 2, H1, W1, H2, W2>
        <<<dim3(B_ * H2 * W2 / 128, C2 / 64), 256>>>(x1, wt2, s2, b2, x2);

    conv_gemm<C2, C3, 2, H2, W2, H3, W3>
        <<<dim3(B_ * H3 * W3 / 128, C3 / 64), 256>>>(x2, wt3, s3, b3, x3);

    conv_gemm<C3, C4, 2, H3, W3, HF, WF>
        <<<dim3(B_ * HF * WF / 128, C4 / 64), 256>>>(x3, wt4, s4, b4, x4);

    conv_gemm<C4, C4, 1, HF, WF, HF, WF>
        <<<dim3(B_ * HF * WF / 128, C4 / 64), 256>>>(x4, wt5, fs1, fb1, fhp);

    heads_splat<<<B_ * HF * WF, 128>>>(x4, fhp, fw2, fb2, dw, db, ow, ob,
                                       camK, Tlc, imgh, imgw);

    finalize_kernel<<<B_ * SV / 32, 256>>>(out);
}